// round 14
// baseline (speedup 1.0000x reference)
#include <cuda_runtime.h>
#include <cuda_fp16.h>
#include <cstdint>

#define BATCH 65536
#define DIN   256
#define HDIM  512
#define KDIM  768
#define NDIM  2048

#define BM 128
#define BN 128
#define BK 32
#define KT 24
#define ROWB 80                          // smem row stride (bytes) for 64B payload
#define A16_OFF  0                       // 2 buffers x 128*80 = 20480
#define A16_STG  (128 * ROWB)
#define B_OFF    (2 * A16_STG)           // 3 stages x 128*80 = 30720
#define B_STG    (128 * ROWB)
#define BIAS_OFF (B_OFF + 3 * B_STG)     // 51200
#define SMEM_BYTES (BIAS_OFF + BN * 4)   // 51712

__device__ __half g_Wpack[(size_t)NDIM * KDIM];    // [n][k], n = 4h+g
__device__ float  g_bias[NDIM];

// ---------------- helpers ----------------
__device__ __forceinline__ uint32_t smem_u32(const void* p) {
    uint32_t a;
    asm("{ .reg .u64 t; cvta.to.shared.u64 t, %1; cvt.u32.u64 %0, t; }" : "=r"(a) : "l"(p));
    return a;
}
__device__ __forceinline__ float tanh_ap(float x) {
    float y; asm("tanh.approx.f32 %0, %1;" : "=f"(y) : "f"(x)); return y;
}
__device__ __forceinline__ float sig_ap(float x) { return 0.5f * tanh_ap(0.5f * x) + 0.5f; }

__device__ __forceinline__ void cp16(uint32_t d, const void* s) {
    asm volatile("cp.async.cg.shared.global [%0], [%1], 16;" :: "r"(d), "l"(s) : "memory");
}
__device__ __forceinline__ void cp_commit() {
    asm volatile("cp.async.commit_group;" ::: "memory");
}
#define CP_WAIT(N) asm volatile("cp.async.wait_group %0;" :: "n"(N) : "memory")

__device__ __forceinline__ void ldsm4(uint32_t r[4], uint32_t addr) {
    asm volatile("ldmatrix.sync.aligned.m8n8.x4.shared.b16 {%0,%1,%2,%3}, [%4];"
                 : "=r"(r[0]), "=r"(r[1]), "=r"(r[2]), "=r"(r[3]) : "r"(addr));
}
__device__ __forceinline__ void mma16816(float d[4], const uint32_t a[4],
                                         uint32_t b0, uint32_t b1) {
    asm volatile(
        "mma.sync.aligned.m16n8k16.row.col.f32.f16.f16.f32 "
        "{%0,%1,%2,%3},{%4,%5,%6,%7},{%8,%9},{%0,%1,%2,%3};"
        : "+f"(d[0]), "+f"(d[1]), "+f"(d[2]), "+f"(d[3])
        : "r"(a[0]), "r"(a[1]), "r"(a[2]), "r"(a[3]), "r"(b0), "r"(b1));
}
__device__ __forceinline__ uint32_t pack2(float a, float b) {
    __half2 h = __floats2half2_rn(a, b);
    return *reinterpret_cast<uint32_t*>(&h);
}

// ---------------------------------------------------------------------------
// pack W: Wpack[n][k] fp16, n = 4h+g; bias[n] = bU+bW
// ---------------------------------------------------------------------------
__global__ void pack_w_kernel(const float* __restrict__ U, const float* __restrict__ bU,
                              const float* __restrict__ W, const float* __restrict__ bW) {
    int idx = blockIdx.x * blockDim.x + threadIdx.x;
    const int total = NDIM * KDIM;
    for (int t = idx; t < total; t += gridDim.x * blockDim.x) {
        int n = t / KDIM;
        int k = t - n * KDIM;
        int h = n >> 2, g = n & 3;
        float v = (k < DIN) ? U[((size_t)g * DIN + k) * HDIM + h]
                            : W[((size_t)g * HDIM + (k - DIN)) * HDIM + h];
        g_Wpack[t] = __float2half_rn(v);
    }
    if (idx < NDIM) {
        int h = idx >> 2, g = idx & 3;
        g_bias[idx] = bU[g * HDIM + h] + bW[g * HDIM + h];
    }
}

// ---------------------------------------------------------------------------
// GEMM + fused LSTM, A conversion inlined (no pack_a).
// BM=128 x BN=128, BK=32, KT=24.  A: LDG fp32 -> cvt -> STS (double buffer).
// B: 3-stage cp.async fp16.  8 warps, 2 CTAs/SM.  f32-accumulator MMA.
// ---------------------------------------------------------------------------
__global__ void __launch_bounds__(256, 2)
lstm_gemm_kernel(const float* __restrict__ x, const float* __restrict__ h_old,
                 const float* __restrict__ c_old, float* __restrict__ out) {
    extern __shared__ __align__(1024) char smem[];
    const uint32_t sb = smem_u32(smem);
    const int tid  = threadIdx.x;
    const int lane = tid & 31;
    const int warp = tid >> 5;
    const int warpM = warp & 1;
    const int warpN = warp >> 1;
    const int bM = blockIdx.y * BM;
    const int bN = blockIdx.x * BN;

    float* bs = reinterpret_cast<float*>(smem + BIAS_OFF);
    for (int i = tid; i < BN; i += 256) bs[i] = g_bias[bN + i];

    // ---- A producer: thread owns (row = tid>>1, seg = tid&1) : 16 fp32 ----
    const int arow = tid >> 1;
    const int aseg = tid & 1;
    const float* px = x     + (size_t)(bM + arow) * DIN  + aseg * 16;
    const float* ph = h_old + (size_t)(bM + arow) * HDIM + aseg * 16;
    const uint32_t aSts = sb + A16_OFF + (uint32_t)arow * ROWB + aseg * 32;

    // ---- B producer: 2 chunks/thread: id = tid + i*256, row = id>>2, c = id&3
    const __half* pb0 = g_Wpack + (size_t)(bN + (tid >> 2)) * KDIM + (tid & 3) * 8;
    const __half* pb1 = g_Wpack + (size_t)(bN + ((tid + 256) >> 2)) * KDIM + (tid & 3) * 8;
    const uint32_t bSts0 = sb + B_OFF + (uint32_t)(tid >> 2) * ROWB + (tid & 3) * 16;
    const uint32_t bSts1 = bSts0 + 64 * ROWB;

#define ISSUE_B(KT_)                                                            \
    {                                                                           \
        uint32_t so = (uint32_t)((KT_) % 3) * B_STG;                            \
        size_t ko = (size_t)(KT_) * BK;                                         \
        cp16(bSts0 + so, pb0 + ko);                                             \
        cp16(bSts1 + so, pb1 + ko);                                             \
    }

    float4 ra[4];
#define LDG_A(KT_)                                                              \
    {                                                                           \
        const float* s = ((KT_) < 8) ? (px + (KT_) * BK) : (ph + ((KT_) - 8) * BK); \
        ra[0] = reinterpret_cast<const float4*>(s)[0];                          \
        ra[1] = reinterpret_cast<const float4*>(s)[1];                          \
        ra[2] = reinterpret_cast<const float4*>(s)[2];                          \
        ra[3] = reinterpret_cast<const float4*>(s)[3];                          \
    }

#define CVT_STS_A(BUF_)                                                         \
    {                                                                           \
        uint4 v0, v1;                                                           \
        v0.x = pack2(ra[0].x, ra[0].y); v0.y = pack2(ra[0].z, ra[0].w);         \
        v0.z = pack2(ra[1].x, ra[1].y); v0.w = pack2(ra[1].z, ra[1].w);         \
        v1.x = pack2(ra[2].x, ra[2].y); v1.y = pack2(ra[2].z, ra[2].w);         \
        v1.z = pack2(ra[3].x, ra[3].y); v1.w = pack2(ra[3].z, ra[3].w);         \
        uint32_t d = aSts + (uint32_t)(BUF_) * A16_STG;                         \
        asm volatile("st.shared.v4.b32 [%0], {%1,%2,%3,%4};"                    \
                     :: "r"(d), "r"(v0.x), "r"(v0.y), "r"(v0.z), "r"(v0.w));    \
        asm volatile("st.shared.v4.b32 [%0], {%1,%2,%3,%4};"                    \
                     :: "r"(d + 16), "r"(v1.x), "r"(v1.y), "r"(v1.z), "r"(v1.w));\
    }

    // ---- consumer LDSM bases (stride-80 rows disperse banks; no XOR) ------
    const int lr = ((lane >> 3) & 1) * 8 + (lane & 7);
    const uint32_t aBase = (uint32_t)(warpM * 64 + lr) * ROWB;
    const uint32_t bBase = (uint32_t)(warpN * 32 + lr) * ROWB;
    const uint32_t cHi   = (uint32_t)(lane >> 4);   // 16B-col select

    float acc[16][4];
#pragma unroll
    for (int t = 0; t < 16; t++)
#pragma unroll
        for (int c = 0; c < 4; c++) acc[t][c] = 0.f;

    // prologue
    LDG_A(0);
    ISSUE_B(0); cp_commit();
    ISSUE_B(1); cp_commit();
    CVT_STS_A(0);

    for (int kt = 0; kt < KT; kt++) {
        CP_WAIT(1);
        __syncthreads();                       // A16[kt&1] + B[kt] visible
        if (kt + 2 < KT) { ISSUE_B(kt + 2); }
        cp_commit();
        if (kt + 1 < KT) { LDG_A(kt + 1); }

        const uint32_t aCur = sb + A16_OFF + (uint32_t)(kt & 1) * A16_STG;
        const uint32_t bCur = sb + B_OFF + (uint32_t)(kt % 3) * B_STG;
#pragma unroll
        for (int kk = 0; kk < 2; kk++) {
            const uint32_t cOff = ((uint32_t)kk * 2u + cHi) * 16u;
            uint32_t af[4][4];
#pragma unroll
            for (int mi = 0; mi < 4; mi++)
                ldsm4(af[mi], aCur + aBase + mi * 16 * ROWB + cOff);
            uint32_t bf[2][4];
#pragma unroll
            for (int p = 0; p < 2; p++)
                ldsm4(bf[p], bCur + bBase + p * 16 * ROWB + cOff);
#pragma unroll
            for (int mi = 0; mi < 4; mi++)
#pragma unroll
                for (int p = 0; p < 2; p++)
#pragma unroll
                    for (int j = 0; j < 2; j++)
                        mma16816(acc[mi * 4 + p * 2 + j], af[mi], bf[p][j], bf[p][j + 2]);
        }
        if (kt + 1 < KT) { CVT_STS_A((kt + 1) & 1); }
    }

    // ---------------- fused LSTM epilogue (shfl pairing) -------------------
    float* out_h = out;
    float* out_c = out + (size_t)BATCH * HDIM;
    const int rBase = bM + warpM * 64 + (lane >> 2) + ((lane & 1) ? 8 : 0);
    const int odd = lane & 1;
#pragma unroll
    for (int mi = 0; mi < 4; mi++)
#pragma unroll
        for (int p = 0; p < 2; p++)
#pragma unroll
            for (int j = 0; j < 2; j++) {
                float* a = acc[mi * 4 + p * 2 + j];
                float t0 = __shfl_xor_sync(0xFFFFFFFFu, a[0], 1);
                float t1 = __shfl_xor_sync(0xFFFFFFFFu, a[1], 1);
                float t2 = __shfl_xor_sync(0xFFFFFFFFu, a[2], 1);
                float t3 = __shfl_xor_sync(0xFFFFFFFFu, a[3], 1);
                int nb = warpN * 32 + p * 16 + j * 8 + 2 * (lane & 3);
                int hl = nb >> 2;
                float4 b4 = *reinterpret_cast<const float4*>(bs + hl * 4);
                int hg = (bN >> 2) + hl;
                int rg = rBase + mi * 16;
                float vi = odd ? t2 : a[0];
                float vf = odd ? t3 : a[1];
                float vo = odd ? a[2] : t0;
                float vc = odd ? a[3] : t1;
                float gi = sig_ap(vi + b4.x);
                float gf = sig_ap(vf + b4.y);
                float go = sig_ap(vo + b4.z);
                float gc = tanh_ap(vc + b4.w);
                float co = c_old[(size_t)rg * HDIM + hg];
                float cn = fmaf(gf, co, gi * gc);
                out_c[(size_t)rg * HDIM + hg] = cn;
                out_h[(size_t)rg * HDIM + hg] = go * tanh_ap(cn);
            }
}

// ---------------------------------------------------------------------------
extern "C" void kernel_launch(void* const* d_in, const int* in_sizes, int n_in,
                              void* d_out, int out_size) {
    const float* x     = (const float*)d_in[0];
    const float* h_old = (const float*)d_in[1];
    const float* c_old = (const float*)d_in[2];
    const float* U     = (const float*)d_in[3];
    const float* bU    = (const float*)d_in[4];
    const float* W     = (const float*)d_in[5];
    const float* bW    = (const float*)d_in[6];
    float* out = (float*)d_out;

    pack_w_kernel<<<1536, 256>>>(U, bU, W, bW);

    cudaFuncSetAttribute(lstm_gemm_kernel,
                         cudaFuncAttributeMaxDynamicSharedMemorySize, SMEM_BYTES);
    dim3 grid(NDIM / BN, BATCH / BM);   // (16, 512), N fastest -> A slices L2-resident
    lstm_gemm_kernel<<<grid, 256, SMEM_BYTES>>>(x, h_old, c_old, out);
}

// round 17
// speedup vs baseline: 1.3707x; 1.3707x over previous
#include <cuda_runtime.h>
#include <cuda_fp16.h>
#include <cstdint>

#define BATCH 65536
#define DIN   256
#define HDIM  512
#define KDIM  768
#define NDIM  2048

#define BM 128
#define BN 128
#define BK 64
#define KT 12
#define STAGES 3
#define ASTG 16384                       // 128 rows x 128B
#define BSTG 16384
#define STG_BYTES (ASTG + BSTG)          // 32768
#define BIAS_OFF (STAGES * STG_BYTES)    // 98304
#define SMEM_BYTES (BIAS_OFF + BN * 4)   // 98816

__device__ __half g_Apack[(size_t)BATCH * KDIM];   // [b][k], k = [x | h]
__device__ __half g_Wpack[(size_t)NDIM * KDIM];    // [n][k], n = 4h+g
__device__ float  g_bias[NDIM];

// ---------------- helpers ----------------
__device__ __forceinline__ uint32_t smem_u32(const void* p) {
    uint32_t a;
    asm("{ .reg .u64 t; cvta.to.shared.u64 t, %1; cvt.u32.u64 %0, t; }" : "=r"(a) : "l"(p));
    return a;
}
__device__ __forceinline__ float tanh_ap(float x) {
    float y; asm("tanh.approx.f32 %0, %1;" : "=f"(y) : "f"(x)); return y;
}
__device__ __forceinline__ float sig_ap(float x) { return 0.5f * tanh_ap(0.5f * x) + 0.5f; }

__device__ __forceinline__ void cp16(uint32_t d, const void* s) {
    asm volatile("cp.async.cg.shared.global [%0], [%1], 16;" :: "r"(d), "l"(s) : "memory");
}
__device__ __forceinline__ void cp_commit() {
    asm volatile("cp.async.commit_group;" ::: "memory");
}
#define CP_WAIT(N) asm volatile("cp.async.wait_group %0;" :: "n"(N) : "memory")

__device__ __forceinline__ void ldsm4(uint32_t r[4], uint32_t addr) {
    asm volatile("ldmatrix.sync.aligned.m8n8.x4.shared.b16 {%0,%1,%2,%3}, [%4];"
                 : "=r"(r[0]), "=r"(r[1]), "=r"(r[2]), "=r"(r[3]) : "r"(addr));
}
__device__ __forceinline__ void mma16816(float d[4], const uint32_t a[4],
                                         uint32_t b0, uint32_t b1) {
    asm volatile(
        "mma.sync.aligned.m16n8k16.row.col.f32.f16.f16.f32 "
        "{%0,%1,%2,%3},{%4,%5,%6,%7},{%8,%9},{%0,%1,%2,%3};"
        : "+f"(d[0]), "+f"(d[1]), "+f"(d[2]), "+f"(d[3])
        : "r"(a[0]), "r"(a[1]), "r"(a[2]), "r"(a[3]), "r"(b0), "r"(b1));
}

// ---------------------------------------------------------------------------
// Merged pack: A = [x|h] fp16 chunks, then W fp16 (n = 4h+g) + fused bias.
// One launch; W work overlaps A tail across blocks.
// ---------------------------------------------------------------------------
__global__ void pack_all_kernel(const float* __restrict__ x, const float* __restrict__ h,
                                const float* __restrict__ U, const float* __restrict__ bU,
                                const float* __restrict__ W, const float* __restrict__ bW) {
    const size_t gstride = (size_t)gridDim.x * blockDim.x;
    const size_t gid0 = (size_t)blockIdx.x * blockDim.x + threadIdx.x;

    // ---- phase 1: A chunks (96 x 16B per row) ----
    const size_t nch = (size_t)BATCH * 96;
    for (size_t id = gid0; id < nch; id += gstride) {
        size_t r = id / 96;
        int c = (int)(id % 96);
        const float* src = (c < 32) ? (x + r * DIN + c * 8) : (h + r * HDIM + (c - 32) * 8);
        float4 f0 = reinterpret_cast<const float4*>(src)[0];
        float4 f1 = reinterpret_cast<const float4*>(src)[1];
        __half2 h0 = __floats2half2_rn(f0.x, f0.y), h1 = __floats2half2_rn(f0.z, f0.w);
        __half2 h2 = __floats2half2_rn(f1.x, f1.y), h3 = __floats2half2_rn(f1.z, f1.w);
        uint4 v;
        v.x = *reinterpret_cast<uint32_t*>(&h0); v.y = *reinterpret_cast<uint32_t*>(&h1);
        v.z = *reinterpret_cast<uint32_t*>(&h2); v.w = *reinterpret_cast<uint32_t*>(&h3);
        reinterpret_cast<uint4*>(g_Apack + r * KDIM)[c] = v;
    }

    // ---- phase 2: W elements ----
    const size_t totalw = (size_t)NDIM * KDIM;
    for (size_t t = gid0; t < totalw; t += gstride) {
        int n = (int)(t / KDIM);
        int k = (int)(t - (size_t)n * KDIM);
        int hh = n >> 2, g = n & 3;
        float v = (k < DIN) ? U[((size_t)g * DIN + k) * HDIM + hh]
                            : W[((size_t)g * HDIM + (k - DIN)) * HDIM + hh];
        g_Wpack[t] = __float2half_rn(v);
    }

    // ---- phase 3: bias ----
    if (gid0 < NDIM) {
        int hh = (int)gid0 >> 2, g = (int)gid0 & 3;
        g_bias[gid0] = bU[g * HDIM + hh] + bW[g * HDIM + hh];
    }
}

// ---------------------------------------------------------------------------
// GEMM + fused LSTM.  BM=128 x BN=128, BK=64, 3-stage cp.async, 8 warps,
// 2 CTAs/SM; single barrier per k-tile; minimal addressing registers.
// (Exact R6 structure — measured 743.7us total, GEMM at ~98% of HMMA floor.)
// ---------------------------------------------------------------------------
__global__ void __launch_bounds__(256, 2)
lstm_gemm_kernel(const float* __restrict__ c_old, float* __restrict__ out) {
    extern __shared__ __align__(1024) char smem[];
    const uint32_t sb = smem_u32(smem);
    const int tid  = threadIdx.x;
    const int lane = tid & 31;
    const int warp = tid >> 5;
    const int warpM = warp & 1;
    const int warpN = warp >> 1;
    const int bM = blockIdx.y * BM;
    const int bN = blockIdx.x * BN;

    float* bs = reinterpret_cast<float*>(smem + BIAS_OFF);
    for (int i = tid; i < BN; i += 256) bs[i] = g_bias[bN + i];

    // producer bases: thread owns (row r = tid>>3 (+32*i), chunk c = tid&7)
    const int pr = tid >> 3;
    const int pc = tid & 7;
    const __half* srcA0 = g_Apack + (size_t)(bM + pr) * KDIM + pc * 8;
    const __half* srcB0 = g_Wpack + (size_t)(bN + pr) * KDIM + pc * 8;
    const uint32_t dstA0 = sb + pr * 128 + (((uint32_t)pc ^ (pr & 7)) << 4);
    const uint32_t dstB0 = dstA0 + ASTG;   // same row/chunk pattern

#define ISSUE(KT_)                                                              \
    {                                                                           \
        uint32_t so = (uint32_t)((KT_) % STAGES) * STG_BYTES;                   \
        size_t ko = (size_t)(KT_) * BK;                                         \
        _Pragma("unroll")                                                       \
        for (int i = 0; i < 4; i++)                                             \
            cp16(dstA0 + so + i * 32 * 128, srcA0 + ko + (size_t)i * 32 * KDIM);\
        _Pragma("unroll")                                                       \
        for (int i = 0; i < 4; i++)                                             \
            cp16(dstB0 + so + i * 32 * 128, srcB0 + ko + (size_t)i * 32 * KDIM);\
    }

    // consumer LDSM bases: swizzle invariant under +16 rows
    const int lr = ((lane >> 3) & 1) * 8 + (lane & 7);
    const uint32_t aBase = (uint32_t)(warpM * 64 + lr) * 128u;
    const uint32_t aSwz  = (uint32_t)((warpM * 64 + lr) & 7);
    const uint32_t bBase = (uint32_t)ASTG + (uint32_t)(warpN * 32 + lr) * 128u;
    const uint32_t bSwz  = (uint32_t)((warpN * 32 + lr) & 7);
    const uint32_t cHi   = (uint32_t)(lane >> 4);

    float acc[16][4];
#pragma unroll
    for (int t = 0; t < 16; t++)
#pragma unroll
        for (int c = 0; c < 4; c++) acc[t][c] = 0.f;

    ISSUE(0); cp_commit();
    ISSUE(1); cp_commit();

    for (int kt = 0; kt < KT; kt++) {
        CP_WAIT(1);
        __syncthreads();
        if (kt + 2 < KT) { ISSUE(kt + 2); }
        cp_commit();

        const uint32_t stg = sb + (uint32_t)(kt % STAGES) * STG_BYTES;
#pragma unroll
        for (int kk = 0; kk < 4; kk++) {
            const uint32_t cc = (uint32_t)kk * 2u + cHi;
            uint32_t af[4][4];
#pragma unroll
            for (int mi = 0; mi < 4; mi++)
                ldsm4(af[mi], stg + aBase + mi * 16 * 128 + ((cc ^ aSwz) << 4));
            uint32_t bf[2][4];
#pragma unroll
            for (int p = 0; p < 2; p++)
                ldsm4(bf[p], stg + bBase + p * 16 * 128 + ((cc ^ bSwz) << 4));
#pragma unroll
            for (int mi = 0; mi < 4; mi++)
#pragma unroll
                for (int p = 0; p < 2; p++)
#pragma unroll
                    for (int j = 0; j < 2; j++)
                        mma16816(acc[mi * 4 + p * 2 + j], af[mi], bf[p][j], bf[p][j + 2]);
        }
    }

    // ---------------- fused LSTM epilogue (shfl pairing) -------------------
    float* out_h = out;
    float* out_c = out + (size_t)BATCH * HDIM;
    const int rBase = bM + warpM * 64 + (lane >> 2) + ((lane & 1) ? 8 : 0);
    const int odd = lane & 1;
#pragma unroll
    for (int mi = 0; mi < 4; mi++)
#pragma unroll
        for (int p = 0; p < 2; p++)
#pragma unroll
            for (int j = 0; j < 2; j++) {
                float* a = acc[mi * 4 + p * 2 + j];
                float t0 = __shfl_xor_sync(0xFFFFFFFFu, a[0], 1);
                float t1 = __shfl_xor_sync(0xFFFFFFFFu, a[1], 1);
                float t2 = __shfl_xor_sync(0xFFFFFFFFu, a[2], 1);
                float t3 = __shfl_xor_sync(0xFFFFFFFFu, a[3], 1);
                int nb = warpN * 32 + p * 16 + j * 8 + 2 * (lane & 3);
                int hl = nb >> 2;
                float4 b4 = *reinterpret_cast<const float4*>(bs + hl * 4);
                int hg = (bN >> 2) + hl;
                int rg = rBase + mi * 16;
                float vi = odd ? t2 : a[0];
                float vf = odd ? t3 : a[1];
                float vo = odd ? a[2] : t0;
                float vc = odd ? a[3] : t1;
                float gi = sig_ap(vi + b4.x);
                float gf = sig_ap(vf + b4.y);
                float go = sig_ap(vo + b4.z);
                float gc = tanh_ap(vc + b4.w);
                float co = c_old[(size_t)rg * HDIM + hg];
                float cn = fmaf(gf, co, gi * gc);
                out_c[(size_t)rg * HDIM + hg] = cn;
                out_h[(size_t)rg * HDIM + hg] = go * tanh_ap(cn);
            }
}

// ---------------------------------------------------------------------------
extern "C" void kernel_launch(void* const* d_in, const int* in_sizes, int n_in,
                              void* d_out, int out_size) {
    const float* x     = (const float*)d_in[0];
    const float* h_old = (const float*)d_in[1];
    const float* c_old = (const float*)d_in[2];
    const float* U     = (const float*)d_in[3];
    const float* bU    = (const float*)d_in[4];
    const float* W     = (const float*)d_in[5];
    const float* bW    = (const float*)d_in[6];
    float* out = (float*)d_out;

    pack_all_kernel<<<2048, 512>>>(x, h_old, U, bU, W, bW);

    cudaFuncSetAttribute(lstm_gemm_kernel,
                         cudaFuncAttributeMaxDynamicSharedMemorySize, SMEM_BYTES);
    dim3 grid(NDIM / BN, BATCH / BM);   // (16, 512), N fastest -> A tiles L2-resident
    lstm_gemm_kernel<<<grid, 256, SMEM_BYTES>>>(c_old, out);
}